// round 12
// baseline (speedup 1.0000x reference)
#include <cuda_runtime.h>
#include <cuda_fp16.h>
#include <cstdint>

#define NN 16384
#define BATCH 2048

typedef unsigned long long ull;

__device__ __forceinline__ uint32_t smem_u32(const void* p) {
    uint32_t a;
    asm("{ .reg .u64 t; cvta.to.shared.u64 t, %1; cvt.u32.u64 %0, t; }" : "=r"(a) : "l"(p));
    return a;
}

// Scratch
__device__ float g_pred_e[BATCH * 1536];
__device__ __align__(16) unsigned short g_h_h[NN * 80];        // h fp16, pitch 80 (k64=1, 65..79=0)
__device__ __align__(16) unsigned short g_x16[BATCH * 768];    // [x_hi | x_lo | x_hi]
__device__ __align__(16) unsigned short g_w16[1536 * 768];     // per col: [W_hi ; W_hi ; W_lo]
__device__ __align__(16) unsigned short g_wd16d[6144 * 80];    // Wd packed [chunk][tile][comp][dd][k80]
__device__ float g_row[4096];
__device__ float g_part[1024];
__device__ unsigned int g_done;

// ---------------------------------------------------------------------------
// K0: prep. blocks 0..2047: x hi/lo split. 2048..2431: We transpose+split.
// 2432..2815: Wd pack into k3 column order (k 0..63). 2816..2839: bias+pad.
// ---------------------------------------------------------------------------
__global__ __launch_bounds__(256) void k0_prep(const float* __restrict__ x,
                                               const float* __restrict__ We,
                                               const float* __restrict__ Wd,
                                               const float* __restrict__ bd) {
    __shared__ float tile[32][33];
    const int b = blockIdx.x;
    const int t = threadIdx.x;
    if (b < 2048) {
        int i = b * 256 + t;
        if (i == 0) g_done = 0;
        int r = i >> 8, c = i & 255;
        float v = x[i];
        __half hi = __float2half_rn(v);
        __half lo = __float2half_rn(v - __half2float(hi));
        g_x16[r * 768 + c]       = __half_as_ushort(hi);
        g_x16[r * 768 + 256 + c] = __half_as_ushort(lo);
        g_x16[r * 768 + 512 + c] = __half_as_ushort(hi);
    } else if (b < 2432) {
        int wb = b - 2048;           // 0..383
        int bk = wb & 7, bn = wb >> 3;
        int tx = t & 31, ty = t >> 5;
#pragma unroll
        for (int s = 0; s < 4; s++)
            tile[ty + 8 * s][tx] = We[(bk * 32 + ty + 8 * s) * 1536 + bn * 32 + tx];
        __syncthreads();
#pragma unroll
        for (int s = 0; s < 4; s++) {
            int nl = ty + 8 * s;
            float v = tile[tx][nl];
            __half hi = __float2half_rn(v);
            __half lo = __float2half_rn(v - __half2float(hi));
            unsigned short* gw = g_w16 + (bn * 32 + nl) * 768 + bk * 32 + tx;
            gw[0]   = __half_as_ushort(hi);
            gw[256] = __half_as_ushort(hi);
            gw[512] = __half_as_ushort(lo);
        }
    } else if (b < 2816) {
        // Wd pack: 2 k-tiles x 192 s-tiles of 32x32
        int wb = b - 2432;
        int bk = wb & 1, bs = wb >> 1;
        int tx = t & 31, ty = t >> 5;
#pragma unroll
        for (int s = 0; s < 4; s++)
            tile[ty + 8 * s][tx] = Wd[(bk * 32 + ty + 8 * s) * 6144 + bs * 32 + tx];
        __syncthreads();
        int s = bs * 32 + tx;
        int dd = s & 15, chunk = (s >> 4) & 15, comp = (s >> 8) & 7, tl = s >> 11;
        int dest = chunk * 384 + tl * 128 + comp * 16 + dd;
        __half2 p0 = __floats2half2_rn(tile[ty * 4 + 0][tx], tile[ty * 4 + 1][tx]);
        __half2 p1 = __floats2half2_rn(tile[ty * 4 + 2][tx], tile[ty * 4 + 3][tx]);
        uint2 u;
        u.x = *(uint32_t*)&p0;
        u.y = *(uint32_t*)&p1;
        *(uint2*)&g_wd16d[dest * 80 + bk * 32 + ty * 4] = u;
    } else {
        // bias (k=64) + zero pad (65..79), dest-ordered
        int cd = (b - 2816) * 256 + t;
        int chunk = cd / 384;
        int rem = cd - chunk * 384;
        int tl = rem >> 7, comp = (rem >> 4) & 7, dd = rem & 15;
        int gcol = tl * 2048 + comp * 256 + chunk * 16 + dd;
        __half hb = __float2half_rn(bd[gcol]);
        uint4 first;
        first.x = (uint32_t)__half_as_ushort(hb);
        first.y = 0; first.z = 0; first.w = 0;
        uint4 z = {0, 0, 0, 0};
        *(uint4*)&g_wd16d[cd * 80 + 64] = first;
        *(uint4*)&g_wd16d[cd * 80 + 72] = z;
    }
}

// ---------------------------------------------------------------------------
// K1: encoder GEMM on HMMA. pred_e[2048x1536] = A[2048x768]*B[768x1536]+be
// ---------------------------------------------------------------------------
#define K1P 72
__global__ __launch_bounds__(256) void k1_hmma(const float* __restrict__ be) {
    __shared__ __align__(16) __half Asm[128 * K1P];
    __shared__ __align__(16) __half Bsm[128 * K1P];
    const int t = threadIdx.x, lane = t & 31, wid = t >> 5;
    const int rwarp = wid & 3, cwarp = wid >> 2;
    const int rows0 = blockIdx.y * 128, cols0 = blockIdx.x * 128;

    float acc[2][4][2][4];
#pragma unroll
    for (int mt = 0; mt < 2; mt++)
#pragma unroll
        for (int p = 0; p < 4; p++)
#pragma unroll
            for (int pr = 0; pr < 2; pr++)
#pragma unroll
                for (int e = 0; e < 4; e++) acc[mt][p][pr][e] = 0.f;

    const uint32_t a_base = smem_u32(Asm) +
        (uint32_t)(((rwarp * 32 + (lane & 15)) * K1P + ((lane >> 4) << 3)) * 2);
    uint32_t b_base;
    {
        int q = lane >> 3;
        int col0 = ((q >= 2) ? 16 : 0) + (lane & 7) + 8 * cwarp;
        b_base = smem_u32(Bsm) + (uint32_t)((col0 * K1P + ((q & 1) << 3)) * 2);
    }

    const __half* gx = (const __half*)g_x16;
    const __half* gw = (const __half*)g_w16;

#pragma unroll 1
    for (int ks = 0; ks < 12; ks++) {
        __syncthreads();
#pragma unroll
        for (int s = 0; s < 4; s++) {
            int idx = t + 256 * s;
            int r = idx >> 3, seg = idx & 7;
            *(uint4*)(Asm + r * K1P + seg * 8) =
                *(const uint4*)(gx + (rows0 + r) * 768 + ks * 64 + seg * 8);
            *(uint4*)(Bsm + r * K1P + seg * 8) =
                *(const uint4*)(gw + (cols0 + r) * 768 + ks * 64 + seg * 8);
        }
        __syncthreads();
#pragma unroll
        for (int kk = 0; kk < 4; kk++) {
            uint32_t a[2][4];
#pragma unroll
            for (int mt = 0; mt < 2; mt++)
                asm volatile("ldmatrix.sync.aligned.m8n8.x4.shared.b16 {%0,%1,%2,%3}, [%4];"
                             : "=r"(a[mt][0]), "=r"(a[mt][1]), "=r"(a[mt][2]), "=r"(a[mt][3])
                             : "r"(a_base + mt * (16 * K1P * 2) + kk * 32));
#pragma unroll
            for (int p = 0; p < 4; p++) {
                uint32_t b0, b1, b2, b3;
                asm volatile("ldmatrix.sync.aligned.m8n8.x4.shared.b16 {%0,%1,%2,%3}, [%4];"
                             : "=r"(b0), "=r"(b1), "=r"(b2), "=r"(b3)
                             : "r"(b_base + p * (32 * K1P * 2) + kk * 32));
#pragma unroll
                for (int mt = 0; mt < 2; mt++) {
                    asm volatile("mma.sync.aligned.m16n8k16.row.col.f32.f16.f16.f32 "
                                 "{%0,%1,%2,%3}, {%4,%5,%6,%7}, {%8,%9}, {%0,%1,%2,%3};"
                                 : "+f"(acc[mt][p][0][0]), "+f"(acc[mt][p][0][1]),
                                   "+f"(acc[mt][p][0][2]), "+f"(acc[mt][p][0][3])
                                 : "r"(a[mt][0]), "r"(a[mt][1]), "r"(a[mt][2]), "r"(a[mt][3]),
                                   "r"(b0), "r"(b1));
                    asm volatile("mma.sync.aligned.m16n8k16.row.col.f32.f16.f16.f32 "
                                 "{%0,%1,%2,%3}, {%4,%5,%6,%7}, {%8,%9}, {%0,%1,%2,%3};"
                                 : "+f"(acc[mt][p][1][0]), "+f"(acc[mt][p][1][1]),
                                   "+f"(acc[mt][p][1][2]), "+f"(acc[mt][p][1][3])
                                 : "r"(a[mt][0]), "r"(a[mt][1]), "r"(a[mt][2]), "r"(a[mt][3]),
                                   "r"(b2), "r"(b3));
                }
            }
        }
    }

    const int groupr = lane >> 2, qr = lane & 3;
#pragma unroll
    for (int p = 0; p < 4; p++)
#pragma unroll
        for (int pr = 0; pr < 2; pr++) {
            const int cb = p * 32 + pr * 16 + 8 * cwarp + 2 * qr;
            const float2 bias = *(const float2*)(be + cols0 + cb);
#pragma unroll
            for (int mt = 0; mt < 2; mt++) {
                const int r0 = rwarp * 32 + mt * 16 + groupr;
                float2 o0 = {acc[mt][p][pr][0] + bias.x, acc[mt][p][pr][1] + bias.y};
                float2 o1 = {acc[mt][p][pr][2] + bias.x, acc[mt][p][pr][3] + bias.y};
                *(float2*)&g_pred_e[(rows0 + r0) * 1536 + cols0 + cb] = o0;
                *(float2*)&g_pred_e[(rows0 + r0 + 8) * 1536 + cols0 + cb] = o1;
            }
        }
}

// ---------------------------------------------------------------------------
// K2: encoder epilogue; writes h fp16 at pitch 80 with pad (k64=1, 65..79=0).
// ---------------------------------------------------------------------------
__global__ __launch_bounds__(256) void k2_encoder(const float* __restrict__ u_e,
                                                  const float* __restrict__ r_in) {
    __shared__ float red[8];
    const int t = threadIdx.x;
    const int n = blockIdx.x * 4 + (t >> 6);
    const int l = t & 63;
    const int b = n & 2047;
    const float* pe = g_pred_e + b * 1536;

    float m[8], lp[8], a[8];
#pragma unroll
    for (int k = 0; k < 8; k++) {
        m[k]  = pe[k * 64 + l];
        lp[k] = pe[512 + k * 64 + l];
        a[k]  = pe[1024 + k * 64 + l];
    }
    float amax = a[0];
#pragma unroll
    for (int k = 1; k < 8; k++) amax = fmaxf(amax, a[k]);
    float e[8];
    float se = 0.f;
#pragma unroll
    for (int k = 0; k < 8; k++) { e[k] = __expf(a[k] - amax); se += e[k]; }
    const float lse_a = amax + __logf(se);
    const float inv_se = 1.f / se;

    const float rv = r_in[n * 64 + l];
    float cacc = 0.f;
    int idx = 0;
#pragma unroll
    for (int k = 0; k < 8; k++) {
        cacc += e[k] * inv_se;
        idx += (rv > cacc) ? 1 : 0;
    }
    if (idx > 7) idx = 7;
    float msel = m[0], lpsel = lp[0];
#pragma unroll
    for (int k = 1; k < 8; k++)
        if (idx == k) { msel = m[k]; lpsel = lp[k]; }
    const float hv = fmaf(__expf(-0.5f * lpsel), u_e[n * 64 + l], msel);
    g_h_h[n * 80 + l] = __half_as_ushort(__float2half_rn(hv));
    if (l < 16)
        g_h_h[n * 80 + 64 + l] = (l == 0) ? __half_as_ushort(__float2half_rn(1.f)) : 0;

    float tv[8];
    float tmax = -1e30f;
#pragma unroll
    for (int k = 0; k < 8; k++) {
        float dh = hv - m[k];
        float v = (a[k] - lse_a) + 0.5f * lp[k] - 0.5f * __expf(lp[k]) * dh * dh;
        tv[k] = v;
        tmax = fmaxf(tmax, v);
    }
    float ts = 0.f;
#pragma unroll
    for (int k = 0; k < 8; k++) ts += __expf(tv[k] - tmax);
    const float Le_l = tmax + __logf(ts);

    float val = -0.5f * hv * hv - Le_l;
#pragma unroll
    for (int off = 16; off > 0; off >>= 1)
        val += __shfl_down_sync(0xffffffffu, val, off);
    if ((t & 31) == 0) red[t >> 5] = val;
    __syncthreads();
    if (t == 0) {
        float s = 0.f;
#pragma unroll
        for (int w = 0; w < 8; w++) s += red[w];
        g_row[blockIdx.x] = s;
    }
}

// ---------------------------------------------------------------------------
// K3: HMMA decoder GEMM + register likelihood + fused final reduce.
// Warp pairs {r, r+4} run decoupled via named barriers; ldmatrix double-
// buffered (A across ks, B across p) to hide LDSM latency.
// ---------------------------------------------------------------------------
#define PITCH 88
#define OFF_W 0
#define OFF_H 67584
#define OFF_X 78848
#define K3_SMEM 82944

__global__ __launch_bounds__(256) void k3_decoder_m(const float* __restrict__ x,
                                                    float* __restrict__ out) {
    extern __shared__ char smem[];
    __shared__ float red[8];
    __shared__ double sred[8];
    __shared__ unsigned int isLast;
    const uint32_t sb = smem_u32(smem);
    const int t = threadIdx.x;
    const int lane = t & 31;
    const int wid = t >> 5;
    const int rwarp = wid & 3;
    const int cwarp = wid >> 2;
    const int pt = cwarp * 32 + lane;        // pair-local thread 0..63
    const int bar_id = 1 + rwarp;
    const int d0 = blockIdx.x * 16;

    __half* wsm = (__half*)(smem + OFF_W);
    __half* hsm = (__half*)(smem + OFF_H);
    float* xsf = (float*)(smem + OFF_X);

    // Stage W: 3840 contiguous uint4 -> pitched smem (whole CTA, once)
    {
        const uint4* wsrc = (const uint4*)g_wd16d + blockIdx.x * 3840;
#pragma unroll
        for (int s = 0; s < 15; s++) {
            int idx = t + 256 * s;
            int c = idx / 10, seg = idx - c * 10;
            *(uint4*)&wsm[c * PITCH + seg * 8] = wsrc[idx];
        }
    }

    const uint32_t a_base = sb + OFF_H +
        (uint32_t)(((rwarp * 16 + (lane & 15)) * PITCH + ((lane >> 4) << 3)) * 2);
    uint32_t b_base;
    {
        int q = lane >> 3;
        int col0 = ((q >= 2) ? 16 : 0) + (lane & 7) + 8 * cwarp;
        b_base = sb + OFF_W + (uint32_t)((col0 * PITCH + (q & 1) * 8) * 2);
    }

    const int groupr = lane >> 2, qr = lane & 3;
    float episum = 0.f;

    __syncthreads();   // W visible to all warps

#pragma unroll 1
    for (int it = 0; it < 4; it++) {
        const int prow0 = blockIdx.y * 256 + it * 64 + rwarp * 16;  // pair's 16 rows
        // wait: both warps of the pair finished reading previous iter's h/x
        asm volatile("bar.sync %0, 64;" :: "r"(bar_id));
        // stage pair's h rows: 160 uint4 over 64 threads
        {
            const __half* hsrc = (const __half*)g_h_h;
#pragma unroll
            for (int s = 0; s < 3; s++) {
                int idx = pt + 64 * s;
                if (idx < 160) {
                    int r = idx / 10, seg = idx - r * 10;
                    *(uint4*)&hsm[(rwarp * 16 + r) * PITCH + seg * 8] =
                        *(const uint4*)(hsrc + (prow0 + r) * 80 + seg * 8);
                }
            }
        }
        // stage pair's x slab: 64 float4
        {
            int r = pt >> 2, d4 = (pt & 3) << 2;
            *(float4*)&xsf[(rwarp * 16 + r) * 16 + d4] =
                *(const float4*)&x[((prow0 + r) & 2047) * 256 + d0 + d4];
        }
        asm volatile("bar.sync %0, 64;" :: "r"(bar_id));

        float acc[24][4];
#pragma unroll
        for (int j = 0; j < 24; j++)
#pragma unroll
            for (int e = 0; e < 4; e++) acc[j][e] = 0.f;

        uint32_t af[2][4], bf[2][4];
        // prologue: A(ks=0), B(ks=0,p=0)
        asm volatile("ldmatrix.sync.aligned.m8n8.x4.shared.b16 {%0,%1,%2,%3}, [%4];"
                     : "=r"(af[0][0]), "=r"(af[0][1]), "=r"(af[0][2]), "=r"(af[0][3])
                     : "r"(a_base));
        asm volatile("ldmatrix.sync.aligned.m8n8.x4.shared.b16 {%0,%1,%2,%3}, [%4];"
                     : "=r"(bf[0][0]), "=r"(bf[0][1]), "=r"(bf[0][2]), "=r"(bf[0][3])
                     : "r"(b_base));
#pragma unroll
        for (int ks = 0; ks < 5; ks++) {
            const int ca = ks & 1, na = ca ^ 1;
            // prefetch A for next ks
            if (ks < 4)
                asm volatile("ldmatrix.sync.aligned.m8n8.x4.shared.b16 {%0,%1,%2,%3}, [%4];"
                             : "=r"(af[na][0]), "=r"(af[na][1]), "=r"(af[na][2]), "=r"(af[na][3])
                             : "r"(a_base + (ks + 1) * 32));
#pragma unroll
            for (int p = 0; p < 12; p++) {
                const int cb = p & 1, nb = cb ^ 1;
                // prefetch B for next p (or p=0 of next ks)
                if (p < 11)
                    asm volatile("ldmatrix.sync.aligned.m8n8.x4.shared.b16 {%0,%1,%2,%3}, [%4];"
                                 : "=r"(bf[nb][0]), "=r"(bf[nb][1]), "=r"(bf[nb][2]), "=r"(bf[nb][3])
                                 : "r"(b_base + (p + 1) * (32 * PITCH * 2) + ks * 32));
                else if (ks < 4)
                    asm volatile("ldmatrix.sync.aligned.m8n8.x4.shared.b16 {%0,%1,%2,%3}, [%4];"
                                 : "=r"(bf[nb][0]), "=r"(bf[nb][1]), "=r"(bf[nb][2]), "=r"(bf[nb][3])
                                 : "r"(b_base + (ks + 1) * 32));
                asm volatile("mma.sync.aligned.m16n8k16.row.col.f32.f16.f16.f32 "
                             "{%0,%1,%2,%3}, {%4,%5,%6,%7}, {%8,%9}, {%0,%1,%2,%3};"
                             : "+f"(acc[2 * p][0]), "+f"(acc[2 * p][1]),
                               "+f"(acc[2 * p][2]), "+f"(acc[2 * p][3])
                             : "r"(af[ca][0]), "r"(af[ca][1]), "r"(af[ca][2]), "r"(af[ca][3]),
                               "r"(bf[cb][0]), "r"(bf[cb][1]));
                asm volatile("mma.sync.aligned.m16n8k16.row.col.f32.f16.f16.f32 "
                             "{%0,%1,%2,%3}, {%4,%5,%6,%7}, {%8,%9}, {%0,%1,%2,%3};"
                             : "+f"(acc[2 * p + 1][0]), "+f"(acc[2 * p + 1][1]),
                               "+f"(acc[2 * p + 1][2]), "+f"(acc[2 * p + 1][3])
                             : "r"(af[ca][0]), "r"(af[ca][1]), "r"(af[ca][2]), "r"(af[ca][3]),
                               "r"(bf[cb][2]), "r"(bf[cb][3]));
            }
        }

#pragma unroll
        for (int hh = 0; hh < 2; hh++) {
            const int r_loc = rwarp * 16 + groupr + 8 * hh;
#pragma unroll
            for (int par = 0; par < 2; par++) {
                const int e = 2 * hh + par;
                const int dd = 8 * cwarp + 2 * qr + par;
                const float xv = xsf[r_loc * 16 + dd];
                float a8[8];
                float amax = -1e30f;
#pragma unroll
                for (int k = 0; k < 8; k++) {
                    a8[k] = acc[16 + k][e];
                    amax = fmaxf(amax, a8[k]);
                }
                float se = 0.f;
#pragma unroll
                for (int k = 0; k < 8; k++) se += __expf(a8[k] - amax);
                const float lse_a = amax + __logf(se);
                float tvv[8];
                float tmax = -1e30f;
#pragma unroll
                for (int k = 0; k < 8; k++) {
                    float lpv = acc[8 + k][e];
                    float dx = xv - acc[k][e];
                    float v = a8[k] + 0.5f * lpv - 0.5f * __expf(lpv) * dx * dx;
                    tvv[k] = v;
                    tmax = fmaxf(tmax, v);
                }
                float ts = 0.f;
#pragma unroll
                for (int k = 0; k < 8; k++) ts += __expf(tvv[k] - tmax);
                episum += tmax + __logf(ts) - lse_a;
            }
        }
    }

    float v = episum;
#pragma unroll
    for (int off = 16; off > 0; off >>= 1)
        v += __shfl_down_sync(0xffffffffu, v, off);
    if (lane == 0) red[wid] = v;
    __syncthreads();
    if (t == 0) {
        float s = 0.f;
#pragma unroll
        for (int w = 0; w < 8; w++) s += red[w];
        g_part[blockIdx.y * 16 + blockIdx.x] = s;
        __threadfence();
        isLast = (atomicAdd(&g_done, 1u) == 1023u) ? 1u : 0u;
    }
    __syncthreads();

    if (isLast) {
        double s = 0.0;
        for (int i = t; i < 1024; i += 256) s += (double)g_part[i];
        for (int i = t; i < 4096; i += 256) s += (double)g_row[i];
#pragma unroll
        for (int off = 16; off > 0; off >>= 1)
            s += __shfl_down_sync(0xffffffffu, s, off);
        if (lane == 0) sred[wid] = s;
        __syncthreads();
        if (wid == 0) {
            double vv = (lane < 8) ? sred[lane] : 0.0;
#pragma unroll
            for (int off = 4; off > 0; off >>= 1)
                vv += __shfl_down_sync(0xffffffffu, vv, off);
            if (lane == 0) {
                out[0] = (float)(-vv / 16384.0 + 128.0 * 1.8378770664093453);
                g_done = 0;
            }
        }
    }
}

extern "C" void kernel_launch(void* const* d_in, const int* in_sizes, int n_in,
                              void* d_out, int out_size) {
    const float* x   = (const float*)d_in[0];
    const float* We  = (const float*)d_in[1];
    const float* be  = (const float*)d_in[2];
    const float* Wd  = (const float*)d_in[3];
    const float* bdv = (const float*)d_in[4];
    const float* ue  = (const float*)d_in[5];
    const float* rr  = (const float*)d_in[6];
    float* out = (float*)d_out;

    static int smem_set = 0;
    if (!smem_set) {
        cudaFuncSetAttribute(k3_decoder_m, cudaFuncAttributeMaxDynamicSharedMemorySize, K3_SMEM);
        smem_set = 1;
    }

    k0_prep<<<2840, 256>>>(x, We, Wd, bdv);
    k1_hmma<<<dim3(12, 16), 256>>>(be);
    k2_encoder<<<4096, 256>>>(ue, rr);
    k3_decoder_m<<<dim3(16, 64), 256, K3_SMEM>>>(x, out);
}

// round 13
// speedup vs baseline: 1.5043x; 1.5043x over previous
#include <cuda_runtime.h>
#include <cuda_fp16.h>
#include <cstdint>

#define NN 16384
#define BATCH 2048

typedef unsigned long long ull;

__device__ __forceinline__ uint32_t smem_u32(const void* p) {
    uint32_t a;
    asm("{ .reg .u64 t; cvta.to.shared.u64 t, %1; cvt.u32.u64 %0, t; }" : "=r"(a) : "l"(p));
    return a;
}

#define CP_ASYNC16(dst, src) \
    asm volatile("cp.async.cg.shared.global [%0], [%1], 16;" :: "r"(dst), "l"(src))
#define CP_COMMIT() asm volatile("cp.async.commit_group;" ::: "memory")
#define CP_WAIT(n)  asm volatile("cp.async.wait_group %0;" :: "n"(n) : "memory")

// Scratch
__device__ float g_pred_e[BATCH * 1536];
__device__ __align__(16) unsigned short g_h_h[NN * 80];        // h fp16, pitch 80 (k64=1, 65..79=0)
__device__ __align__(16) unsigned short g_x16[BATCH * 768];    // [x_hi | x_lo | x_hi]
__device__ __align__(16) unsigned short g_w16[1536 * 768];     // per col: [W_hi ; W_hi ; W_lo]
__device__ __align__(16) unsigned short g_wd16d[6144 * 80];    // Wd packed [chunk][tile][comp][dd][k80]
__device__ float g_row[4096];
__device__ float g_part[1024];
__device__ unsigned int g_done;

// ---------------------------------------------------------------------------
// K0: prep. blocks 0..2047: x hi/lo split. 2048..2431: We transpose+split.
// 2432..2815: Wd pack into k3 column order (k 0..63). 2816..2839: bias+pad.
// ---------------------------------------------------------------------------
__global__ __launch_bounds__(256) void k0_prep(const float* __restrict__ x,
                                               const float* __restrict__ We,
                                               const float* __restrict__ Wd,
                                               const float* __restrict__ bd) {
    __shared__ float tile[32][33];
    const int b = blockIdx.x;
    const int t = threadIdx.x;
    if (b < 2048) {
        int i = b * 256 + t;
        if (i == 0) g_done = 0;
        int r = i >> 8, c = i & 255;
        float v = x[i];
        __half hi = __float2half_rn(v);
        __half lo = __float2half_rn(v - __half2float(hi));
        g_x16[r * 768 + c]       = __half_as_ushort(hi);
        g_x16[r * 768 + 256 + c] = __half_as_ushort(lo);
        g_x16[r * 768 + 512 + c] = __half_as_ushort(hi);
    } else if (b < 2432) {
        int wb = b - 2048;           // 0..383
        int bk = wb & 7, bn = wb >> 3;
        int tx = t & 31, ty = t >> 5;
#pragma unroll
        for (int s = 0; s < 4; s++)
            tile[ty + 8 * s][tx] = We[(bk * 32 + ty + 8 * s) * 1536 + bn * 32 + tx];
        __syncthreads();
#pragma unroll
        for (int s = 0; s < 4; s++) {
            int nl = ty + 8 * s;
            float v = tile[tx][nl];
            __half hi = __float2half_rn(v);
            __half lo = __float2half_rn(v - __half2float(hi));
            unsigned short* gw = g_w16 + (bn * 32 + nl) * 768 + bk * 32 + tx;
            gw[0]   = __half_as_ushort(hi);
            gw[256] = __half_as_ushort(hi);
            gw[512] = __half_as_ushort(lo);
        }
    } else if (b < 2816) {
        // Wd pack: 2 k-tiles x 192 s-tiles of 32x32
        int wb = b - 2432;
        int bk = wb & 1, bs = wb >> 1;
        int tx = t & 31, ty = t >> 5;
#pragma unroll
        for (int s = 0; s < 4; s++)
            tile[ty + 8 * s][tx] = Wd[(bk * 32 + ty + 8 * s) * 6144 + bs * 32 + tx];
        __syncthreads();
        int s = bs * 32 + tx;
        int dd = s & 15, chunk = (s >> 4) & 15, comp = (s >> 8) & 7, tl = s >> 11;
        int dest = chunk * 384 + tl * 128 + comp * 16 + dd;
        __half2 p0 = __floats2half2_rn(tile[ty * 4 + 0][tx], tile[ty * 4 + 1][tx]);
        __half2 p1 = __floats2half2_rn(tile[ty * 4 + 2][tx], tile[ty * 4 + 3][tx]);
        uint2 u;
        u.x = *(uint32_t*)&p0;
        u.y = *(uint32_t*)&p1;
        *(uint2*)&g_wd16d[dest * 80 + bk * 32 + ty * 4] = u;
    } else {
        // bias (k=64) + zero pad (65..79), dest-ordered
        int cd = (b - 2816) * 256 + t;
        int chunk = cd / 384;
        int rem = cd - chunk * 384;
        int tl = rem >> 7, comp = (rem >> 4) & 7, dd = rem & 15;
        int gcol = tl * 2048 + comp * 256 + chunk * 16 + dd;
        __half hb = __float2half_rn(bd[gcol]);
        uint4 first;
        first.x = (uint32_t)__half_as_ushort(hb);
        first.y = 0; first.z = 0; first.w = 0;
        uint4 z = {0, 0, 0, 0};
        *(uint4*)&g_wd16d[cd * 80 + 64] = first;
        *(uint4*)&g_wd16d[cd * 80 + 72] = z;
    }
}

// ---------------------------------------------------------------------------
// K1: encoder GEMM on HMMA. pred_e[2048x1536] = A[2048x768]*B[768x1536]+be
// ---------------------------------------------------------------------------
#define K1P 72
__global__ __launch_bounds__(256) void k1_hmma(const float* __restrict__ be) {
    __shared__ __align__(16) __half Asm[128 * K1P];
    __shared__ __align__(16) __half Bsm[128 * K1P];
    const int t = threadIdx.x, lane = t & 31, wid = t >> 5;
    const int rwarp = wid & 3, cwarp = wid >> 2;
    const int rows0 = blockIdx.y * 128, cols0 = blockIdx.x * 128;

    float acc[2][4][2][4];
#pragma unroll
    for (int mt = 0; mt < 2; mt++)
#pragma unroll
        for (int p = 0; p < 4; p++)
#pragma unroll
            for (int pr = 0; pr < 2; pr++)
#pragma unroll
                for (int e = 0; e < 4; e++) acc[mt][p][pr][e] = 0.f;

    const uint32_t a_base = smem_u32(Asm) +
        (uint32_t)(((rwarp * 32 + (lane & 15)) * K1P + ((lane >> 4) << 3)) * 2);
    uint32_t b_base;
    {
        int q = lane >> 3;
        int col0 = ((q >= 2) ? 16 : 0) + (lane & 7) + 8 * cwarp;
        b_base = smem_u32(Bsm) + (uint32_t)((col0 * K1P + ((q & 1) << 3)) * 2);
    }

    const __half* gx = (const __half*)g_x16;
    const __half* gw = (const __half*)g_w16;

#pragma unroll 1
    for (int ks = 0; ks < 12; ks++) {
        __syncthreads();
#pragma unroll
        for (int s = 0; s < 4; s++) {
            int idx = t + 256 * s;
            int r = idx >> 3, seg = idx & 7;
            *(uint4*)(Asm + r * K1P + seg * 8) =
                *(const uint4*)(gx + (rows0 + r) * 768 + ks * 64 + seg * 8);
            *(uint4*)(Bsm + r * K1P + seg * 8) =
                *(const uint4*)(gw + (cols0 + r) * 768 + ks * 64 + seg * 8);
        }
        __syncthreads();
#pragma unroll
        for (int kk = 0; kk < 4; kk++) {
            uint32_t a[2][4];
#pragma unroll
            for (int mt = 0; mt < 2; mt++)
                asm volatile("ldmatrix.sync.aligned.m8n8.x4.shared.b16 {%0,%1,%2,%3}, [%4];"
                             : "=r"(a[mt][0]), "=r"(a[mt][1]), "=r"(a[mt][2]), "=r"(a[mt][3])
                             : "r"(a_base + mt * (16 * K1P * 2) + kk * 32));
#pragma unroll
            for (int p = 0; p < 4; p++) {
                uint32_t b0, b1, b2, b3;
                asm volatile("ldmatrix.sync.aligned.m8n8.x4.shared.b16 {%0,%1,%2,%3}, [%4];"
                             : "=r"(b0), "=r"(b1), "=r"(b2), "=r"(b3)
                             : "r"(b_base + p * (32 * K1P * 2) + kk * 32));
#pragma unroll
                for (int mt = 0; mt < 2; mt++) {
                    asm volatile("mma.sync.aligned.m16n8k16.row.col.f32.f16.f16.f32 "
                                 "{%0,%1,%2,%3}, {%4,%5,%6,%7}, {%8,%9}, {%0,%1,%2,%3};"
                                 : "+f"(acc[mt][p][0][0]), "+f"(acc[mt][p][0][1]),
                                   "+f"(acc[mt][p][0][2]), "+f"(acc[mt][p][0][3])
                                 : "r"(a[mt][0]), "r"(a[mt][1]), "r"(a[mt][2]), "r"(a[mt][3]),
                                   "r"(b0), "r"(b1));
                    asm volatile("mma.sync.aligned.m16n8k16.row.col.f32.f16.f16.f32 "
                                 "{%0,%1,%2,%3}, {%4,%5,%6,%7}, {%8,%9}, {%0,%1,%2,%3};"
                                 : "+f"(acc[mt][p][1][0]), "+f"(acc[mt][p][1][1]),
                                   "+f"(acc[mt][p][1][2]), "+f"(acc[mt][p][1][3])
                                 : "r"(a[mt][0]), "r"(a[mt][1]), "r"(a[mt][2]), "r"(a[mt][3]),
                                   "r"(b2), "r"(b3));
                }
            }
        }
    }

    const int groupr = lane >> 2, qr = lane & 3;
#pragma unroll
    for (int p = 0; p < 4; p++)
#pragma unroll
        for (int pr = 0; pr < 2; pr++) {
            const int cb = p * 32 + pr * 16 + 8 * cwarp + 2 * qr;
            const float2 bias = *(const float2*)(be + cols0 + cb);
#pragma unroll
            for (int mt = 0; mt < 2; mt++) {
                const int r0 = rwarp * 32 + mt * 16 + groupr;
                float2 o0 = {acc[mt][p][pr][0] + bias.x, acc[mt][p][pr][1] + bias.y};
                float2 o1 = {acc[mt][p][pr][2] + bias.x, acc[mt][p][pr][3] + bias.y};
                *(float2*)&g_pred_e[(rows0 + r0) * 1536 + cols0 + cb] = o0;
                *(float2*)&g_pred_e[(rows0 + r0 + 8) * 1536 + cols0 + cb] = o1;
            }
        }
}

// ---------------------------------------------------------------------------
// K2: encoder epilogue; writes h fp16 at pitch 80 with pad (k64=1, 65..79=0).
// ---------------------------------------------------------------------------
__global__ __launch_bounds__(256) void k2_encoder(const float* __restrict__ u_e,
                                                  const float* __restrict__ r_in) {
    __shared__ float red[8];
    const int t = threadIdx.x;
    const int n = blockIdx.x * 4 + (t >> 6);
    const int l = t & 63;
    const int b = n & 2047;
    const float* pe = g_pred_e + b * 1536;

    float m[8], lp[8], a[8];
#pragma unroll
    for (int k = 0; k < 8; k++) {
        m[k]  = pe[k * 64 + l];
        lp[k] = pe[512 + k * 64 + l];
        a[k]  = pe[1024 + k * 64 + l];
    }
    float amax = a[0];
#pragma unroll
    for (int k = 1; k < 8; k++) amax = fmaxf(amax, a[k]);
    float e[8];
    float se = 0.f;
#pragma unroll
    for (int k = 0; k < 8; k++) { e[k] = __expf(a[k] - amax); se += e[k]; }
    const float lse_a = amax + __logf(se);
    const float inv_se = 1.f / se;

    const float rv = r_in[n * 64 + l];
    float cacc = 0.f;
    int idx = 0;
#pragma unroll
    for (int k = 0; k < 8; k++) {
        cacc += e[k] * inv_se;
        idx += (rv > cacc) ? 1 : 0;
    }
    if (idx > 7) idx = 7;
    float msel = m[0], lpsel = lp[0];
#pragma unroll
    for (int k = 1; k < 8; k++)
        if (idx == k) { msel = m[k]; lpsel = lp[k]; }
    const float hv = fmaf(__expf(-0.5f * lpsel), u_e[n * 64 + l], msel);
    g_h_h[n * 80 + l] = __half_as_ushort(__float2half_rn(hv));
    if (l < 16)
        g_h_h[n * 80 + 64 + l] = (l == 0) ? __half_as_ushort(__float2half_rn(1.f)) : 0;

    float tv[8];
    float tmax = -1e30f;
#pragma unroll
    for (int k = 0; k < 8; k++) {
        float dh = hv - m[k];
        float v = (a[k] - lse_a) + 0.5f * lp[k] - 0.5f * __expf(lp[k]) * dh * dh;
        tv[k] = v;
        tmax = fmaxf(tmax, v);
    }
    float ts = 0.f;
#pragma unroll
    for (int k = 0; k < 8; k++) ts += __expf(tv[k] - tmax);
    const float Le_l = tmax + __logf(ts);

    float val = -0.5f * hv * hv - Le_l;
#pragma unroll
    for (int off = 16; off > 0; off >>= 1)
        val += __shfl_down_sync(0xffffffffu, val, off);
    if ((t & 31) == 0) red[t >> 5] = val;
    __syncthreads();
    if (t == 0) {
        float s = 0.f;
#pragma unroll
        for (int w = 0; w < 8; w++) s += red[w];
        g_row[blockIdx.x] = s;
    }
}

// ---------------------------------------------------------------------------
// K3: HMMA decoder GEMM + register likelihood + fused final reduce.
// R11 compute structure; h/x staged via cp.async double-buffer so global-load
// latency overlaps the previous iteration's MMA+epilogue.
// ---------------------------------------------------------------------------
#define PITCH 88
#define OFF_W  0
#define OFF_H0 67584
#define OFF_H1 78848
#define OFF_X0 90112
#define OFF_X1 94208
#define K3_SMEM 98304

__global__ __launch_bounds__(256) void k3_decoder_m(const float* __restrict__ x,
                                                    float* __restrict__ out) {
    extern __shared__ char smem[];
    __shared__ float red[8];
    __shared__ double sred[8];
    __shared__ unsigned int isLast;
    const uint32_t sb = smem_u32(smem);
    const int t = threadIdx.x;
    const int lane = t & 31;
    const int wid = t >> 5;
    const int rwarp = wid & 3;
    const int cwarp = wid >> 2;
    const int d0 = blockIdx.x * 16;

    __half* wsm = (__half*)(smem + OFF_W);

    // Stage W: 3840 contiguous uint4 -> pitched smem
    {
        const uint4* wsrc = (const uint4*)g_wd16d + blockIdx.x * 3840;
#pragma unroll
        for (int s = 0; s < 15; s++) {
            int idx = t + 256 * s;
            int c = idx / 10, seg = idx - c * 10;
            *(uint4*)&wsm[c * PITCH + seg * 8] = wsrc[idx];
        }
    }

    const uint32_t a_off =
        (uint32_t)(((rwarp * 16 + (lane & 15)) * PITCH + ((lane >> 4) << 3)) * 2);
    uint32_t b_base;
    {
        int q = lane >> 3;
        int col0 = ((q >= 2) ? 16 : 0) + (lane & 7) + 8 * cwarp;
        b_base = sb + OFF_W + (uint32_t)((col0 * PITCH + (q & 1) * 8) * 2);
    }

    const int groupr = lane >> 2, qr = lane & 3;
    const int hr = t / 10, hseg = t - hr * 10;          // h copy: rows 0..25 part
    const int xr = t >> 2, xd4 = (t & 3) << 2;          // x copy
    float episum = 0.f;

    // async stage of iteration `it` into buffer `hb`
    auto stage = [&](int it, int hb) {
        const int row0 = blockIdx.y * 256 + it * 64;
        const uint32_t hdst = sb + (hb ? OFF_H1 : OFF_H0);
        const uint32_t xdst = sb + (hb ? OFF_X1 : OFF_X0);
        const char* hsrc = (const char*)g_h_h;
#pragma unroll
        for (int s = 0; s < 3; s++) {
            int idx = t + 256 * s;
            if (idx < 640) {
                int r = idx / 10, seg = idx - r * 10;
                CP_ASYNC16(hdst + (uint32_t)((r * PITCH + seg * 8) * 2),
                           hsrc + ((size_t)(row0 + r) * 80 + seg * 8) * 2);
            }
        }
        CP_ASYNC16(xdst + (uint32_t)((xr * 16 + xd4) * 4),
                   (const char*)(x + ((size_t)((row0 + xr) & 2047)) * 256 + d0 + xd4));
    };

    stage(0, 0);
    CP_COMMIT();

#pragma unroll 1
    for (int it = 0; it < 4; it++) {
        const int cur = it & 1;
        if (it < 3) {
            stage(it + 1, cur ^ 1);
            CP_COMMIT();
            CP_WAIT(1);
        } else {
            CP_WAIT(0);
        }
        __syncthreads();

        const uint32_t a_base = sb + (cur ? OFF_H1 : OFF_H0) + a_off;
        const float* xsf = (const float*)(smem + (cur ? OFF_X1 : OFF_X0));

        float acc[24][4];
#pragma unroll
        for (int j = 0; j < 24; j++)
#pragma unroll
            for (int e = 0; e < 4; e++) acc[j][e] = 0.f;

#pragma unroll
        for (int ks = 0; ks < 5; ks++) {
            uint32_t a0, a1, a2, a3;
            asm volatile("ldmatrix.sync.aligned.m8n8.x4.shared.b16 {%0,%1,%2,%3}, [%4];"
                         : "=r"(a0), "=r"(a1), "=r"(a2), "=r"(a3)
                         : "r"(a_base + ks * 32));
#pragma unroll
            for (int p = 0; p < 12; p++) {
                uint32_t b0, b1, b2, b3;
                asm volatile("ldmatrix.sync.aligned.m8n8.x4.shared.b16 {%0,%1,%2,%3}, [%4];"
                             : "=r"(b0), "=r"(b1), "=r"(b2), "=r"(b3)
                             : "r"(b_base + p * (32 * PITCH * 2) + ks * 32));
                asm volatile("mma.sync.aligned.m16n8k16.row.col.f32.f16.f16.f32 "
                             "{%0,%1,%2,%3}, {%4,%5,%6,%7}, {%8,%9}, {%0,%1,%2,%3};"
                             : "+f"(acc[2 * p][0]), "+f"(acc[2 * p][1]),
                               "+f"(acc[2 * p][2]), "+f"(acc[2 * p][3])
                             : "r"(a0), "r"(a1), "r"(a2), "r"(a3), "r"(b0), "r"(b1));
                asm volatile("mma.sync.aligned.m16n8k16.row.col.f32.f16.f16.f32 "
                             "{%0,%1,%2,%3}, {%4,%5,%6,%7}, {%8,%9}, {%0,%1,%2,%3};"
                             : "+f"(acc[2 * p + 1][0]), "+f"(acc[2 * p + 1][1]),
                               "+f"(acc[2 * p + 1][2]), "+f"(acc[2 * p + 1][3])
                             : "r"(a0), "r"(a1), "r"(a2), "r"(a3), "r"(b2), "r"(b3));
            }
        }

#pragma unroll
        for (int hh = 0; hh < 2; hh++) {
            const int r_loc = rwarp * 16 + groupr + 8 * hh;
#pragma unroll
            for (int par = 0; par < 2; par++) {
                const int e = 2 * hh + par;
                const int dd = 8 * cwarp + 2 * qr + par;
                const float xv = xsf[r_loc * 16 + dd];
                float a8[8];
                float amax = -1e30f;
#pragma unroll
                for (int k = 0; k < 8; k++) {
                    a8[k] = acc[16 + k][e];
                    amax = fmaxf(amax, a8[k]);
                }
                float se = 0.f;
#pragma unroll
                for (int k = 0; k < 8; k++) se += __expf(a8[k] - amax);
                const float lse_a = amax + __logf(se);
                float tvv[8];
                float tmax = -1e30f;
#pragma unroll
                for (int k = 0; k < 8; k++) {
                    float lpv = acc[8 + k][e];
                    float dx = xv - acc[k][e];
                    float v = a8[k] + 0.5f * lpv - 0.5f * __expf(lpv) * dx * dx;
                    tvv[k] = v;
                    tmax = fmaxf(tmax, v);
                }
                float ts = 0.f;
#pragma unroll
                for (int k = 0; k < 8; k++) ts += __expf(tvv[k] - tmax);
                episum += tmax + __logf(ts) - lse_a;
            }
        }
        __syncthreads();   // all reads of buf[cur] done before restage at it+2
    }

    float v = episum;
#pragma unroll
    for (int off = 16; off > 0; off >>= 1)
        v += __shfl_down_sync(0xffffffffu, v, off);
    if (lane == 0) red[wid] = v;
    __syncthreads();
    if (t == 0) {
        float s = 0.f;
#pragma unroll
        for (int w = 0; w < 8; w++) s += red[w];
        g_part[blockIdx.y * 16 + blockIdx.x] = s;
        __threadfence();
        isLast = (atomicAdd(&g_done, 1u) == 1023u) ? 1u : 0u;
    }
    __syncthreads();

    if (isLast) {
        double s = 0.0;
        for (int i = t; i < 1024; i += 256) s += (double)g_part[i];
        for (int i = t; i < 4096; i += 256) s += (double)g_row[i];
#pragma unroll
        for (int off = 16; off > 0; off >>= 1)
            s += __shfl_down_sync(0xffffffffu, s, off);
        if (lane == 0) sred[wid] = s;
        __syncthreads();
        if (wid == 0) {
            double vv = (lane < 8) ? sred[lane] : 0.0;
#pragma unroll
            for (int off = 4; off > 0; off >>= 1)
                vv += __shfl_down_sync(0xffffffffu, vv, off);
            if (lane == 0) {
                out[0] = (float)(-vv / 16384.0 + 128.0 * 1.8378770664093453);
                g_done = 0;
            }
        }
    }
}

extern "C" void kernel_launch(void* const* d_in, const int* in_sizes, int n_in,
                              void* d_out, int out_size) {
    const float* x   = (const float*)d_in[0];
    const float* We  = (const float*)d_in[1];
    const float* be  = (const float*)d_in[2];
    const float* Wd  = (const float*)d_in[3];
    const float* bdv = (const float*)d_in[4];
    const float* ue  = (const float*)d_in[5];
    const float* rr  = (const float*)d_in[6];
    float* out = (float*)d_out;

    static int smem_set = 0;
    if (!smem_set) {
        cudaFuncSetAttribute(k3_decoder_m, cudaFuncAttributeMaxDynamicSharedMemorySize, K3_SMEM);
        smem_set = 1;
    }

    k0_prep<<<2840, 256>>>(x, We, Wd, bdv);
    k1_hmma<<<dim3(12, 16), 256>>>(be);
    k2_encoder<<<4096, 256>>>(ue, rr);
    k3_decoder_m<<<dim3(16, 64), 256, K3_SMEM>>>(x, out);
}